// round 3
// baseline (speedup 1.0000x reference)
#include <cuda_runtime.h>
#include <cuda_bf16.h>
#include <cstdint>

#define N_NODES 100000
#define N_EDGES 1600000
#define IN_FEAT 128
#define UNITS   64

// ---------------- scratch (device globals: alloc-free rule) ----------------
__device__ float g_h[(size_t)N_NODES * UNITS];       // 25.6 MB
__device__ float g_adst[N_NODES];
__device__ float g_asrc[N_NODES];
__device__ int   g_rowptr[N_NODES + 1];
__device__ float g_p[N_EDGES];                       // exp'd scores, 6.4 MB
__device__ int   g_dst[N_EDGES];                     // unpacked dst (int32)
__device__ int   g_src[N_EDGES];                     // unpacked src (int32)
__device__ int   g_is64;                             // edge dtype flag

// ---------------------------------------------------------------------------
// Kernel 0a: detect whether the edge buffer is int64 or int32.
// For int64 (all values in [0, 2^31)), every odd 32-bit word is a zero
// high-word. For int32 the odd words are random src node ids.
// ---------------------------------------------------------------------------
__global__ void gat_detect_kernel(const unsigned int* __restrict__ e32)
{
    if (threadIdx.x == 0 && blockIdx.x == 0) {
        int all_zero = 1;
        #pragma unroll
        for (int i = 0; i < 32; i++)
            if (e32[2 * i + 1] != 0u) { all_zero = 0; break; }
        g_is64 = all_zero;
    }
}

// ---------------------------------------------------------------------------
// Kernel 0b: unpack edges -> flat int32 dst/src arrays (dtype-agnostic).
// ---------------------------------------------------------------------------
__global__ void gat_unpack_kernel(const unsigned int* __restrict__ e32)
{
    int i = blockIdx.x * blockDim.x + threadIdx.x;
    if (i >= N_EDGES) return;
    if (g_is64) {
        g_dst[i] = (int)e32[4 * (size_t)i];       // low word of edges[i][0]
        g_src[i] = (int)e32[4 * (size_t)i + 2];   // low word of edges[i][1]
    } else {
        g_dst[i] = (int)e32[2 * (size_t)i];
        g_src[i] = (int)e32[2 * (size_t)i + 1];
    }
}

// ---------------------------------------------------------------------------
// Kernel 1: tiled GEMM  h = X(100000x128) @ K(128x64), fused per-row
//           a_dst = h . ka[0:64], a_src = h . ka[64:128]
// Block: 256 threads, 32 rows per block. Static smem: 32KB (K) + 16KB (X).
// Thread microtile: 2 rows x 4 cols. 100000 % 32 == 0 -> no bounds checks.
// ---------------------------------------------------------------------------
#define TM 32

__global__ void __launch_bounds__(256, 4)
gat_gemm_kernel(const float* __restrict__ X,
                const float* __restrict__ K,
                const float* __restrict__ KA)
{
    __shared__ float Ks[IN_FEAT * UNITS];   // 32 KB
    __shared__ float Xs[TM * IN_FEAT];      // 16 KB

    const int tid  = threadIdx.x;
    const int row0 = blockIdx.x * TM;

    {
        const float4* K4 = (const float4*)K;
        float4* Ks4 = (float4*)Ks;
        #pragma unroll
        for (int i = tid; i < (IN_FEAT * UNITS) / 4; i += 256)
            Ks4[i] = K4[i];
    }
    {
        const float4* X4 = (const float4*)X;
        float4* Xs4 = (float4*)Xs;
        #pragma unroll
        for (int i = tid; i < TM * (IN_FEAT / 4); i += 256)
            Xs4[i] = X4[(size_t)row0 * (IN_FEAT / 4) + i];
    }
    __syncthreads();

    const int colb = tid & 15;          // 16 col groups of 4 cols
    const int rowb = tid >> 4;          // 16 row groups of 2 rows
    const int c0 = colb * 4;
    const int r0 = rowb * 2;

    float acc[2][4];
    #pragma unroll
    for (int r = 0; r < 2; r++)
        #pragma unroll
        for (int c = 0; c < 4; c++)
            acc[r][c] = 0.f;

    #pragma unroll 4
    for (int k = 0; k < IN_FEAT; k++) {
        float4 kv = *(const float4*)&Ks[k * UNITS + c0];
        #pragma unroll
        for (int r = 0; r < 2; r++) {
            float xv = Xs[(r0 + r) * IN_FEAT + k];
            acc[r][0] = fmaf(xv, kv.x, acc[r][0]);
            acc[r][1] = fmaf(xv, kv.y, acc[r][1]);
            acc[r][2] = fmaf(xv, kv.z, acc[r][2]);
            acc[r][3] = fmaf(xv, kv.w, acc[r][3]);
        }
    }

    #pragma unroll
    for (int r = 0; r < 2; r++) {
        int row = row0 + r0 + r;
        float4 v = make_float4(acc[r][0], acc[r][1], acc[r][2], acc[r][3]);
        *(float4*)&g_h[(size_t)row * UNITS + c0] = v;
    }

    // fused attention logits
    float ka0[4], ka1[4];
    #pragma unroll
    for (int j = 0; j < 4; j++) {
        ka0[j] = KA[c0 + j];            // dst half
        ka1[j] = KA[UNITS + c0 + j];    // src half
    }
    #pragma unroll
    for (int r = 0; r < 2; r++) {
        float p0 = acc[r][0] * ka0[0] + acc[r][1] * ka0[1]
                 + acc[r][2] * ka0[2] + acc[r][3] * ka0[3];
        float p1 = acc[r][0] * ka1[0] + acc[r][1] * ka1[1]
                 + acc[r][2] * ka1[2] + acc[r][3] * ka1[3];
        #pragma unroll
        for (int o = 8; o > 0; o >>= 1) {
            p0 += __shfl_down_sync(0xffffffffu, p0, o, 16);
            p1 += __shfl_down_sync(0xffffffffu, p1, o, 16);
        }
        if (colb == 0) {
            int row = row0 + r0 + r;
            g_adst[row] = p0;
            g_asrc[row] = p1;
        }
    }
}

// ---------------------------------------------------------------------------
// Kernel 2: CSR row-ptr from sorted dst
// ---------------------------------------------------------------------------
__global__ void gat_rowptr_kernel()
{
    int i = blockIdx.x * blockDim.x + threadIdx.x;
    if (i >= N_EDGES) return;
    int d     = g_dst[i];
    int dprev = (i == 0) ? -1 : g_dst[i - 1];
    for (int n = dprev + 1; n <= d; n++) g_rowptr[n] = i;
    if (i == N_EDGES - 1)
        for (int n = d + 1; n <= N_NODES; n++) g_rowptr[n] = N_EDGES;
}

// ---------------------------------------------------------------------------
// Kernel 3: fused edge softmax + weighted scatter. One warp per node.
// ---------------------------------------------------------------------------
__global__ void __launch_bounds__(256)
gat_attn_kernel(float* __restrict__ out)
{
    int gtid = blockIdx.x * blockDim.x + threadIdx.x;
    int node = gtid >> 5;
    int lane = gtid & 31;
    if (node >= N_NODES) return;

    int start = g_rowptr[node];
    int end   = g_rowptr[node + 1];
    float ad  = g_adst[node];

    // Pass A: scores + warp segment sum
    float sum = 0.f;
    for (int e = start + lane; e < end; e += 32) {
        int s = g_src[e];
        float sc = ad + g_asrc[s];
        sc = (sc > 0.f) ? sc : 0.2f * sc;       // leaky_relu(0.2)
        sc = fminf(fmaxf(sc, -2.f), 2.f);       // clip
        float p = __expf(sc);
        g_p[e] = p;
        sum += p;
    }
    #pragma unroll
    for (int o = 16; o > 0; o >>= 1)
        sum += __shfl_xor_sync(0xffffffffu, sum, o);
    __syncwarp();   // memory-order g_p writes before pass B reads

    float inv = (end > start) ? (1.f / sum) : 0.f;

    // Pass B: gather h[src] rows, accumulate weighted sum in registers
    float a0 = 0.f, a1 = 0.f;
    for (int e = start; e < end; e++) {
        int s = g_src[e];
        float attn = g_p[e] * inv;
        const float* hrow = &g_h[(size_t)s * UNITS];
        a0 = fmaf(hrow[lane],      attn, a0);
        a1 = fmaf(hrow[lane + 32], attn, a1);
    }
    out[(size_t)node * UNITS + lane]      = a0;
    out[(size_t)node * UNITS + lane + 32] = a1;
}

// ---------------------------------------------------------------------------
extern "C" void kernel_launch(void* const* d_in, const int* in_sizes, int n_in,
                              void* d_out, int out_size)
{
    const float*        X   = (const float*)d_in[0];        // node_states
    const unsigned int* E32 = (const unsigned int*)d_in[1]; // edges (int32 or int64)
    const float*        K   = (const float*)d_in[2];        // kernel [128,64]
    const float*        KA  = (const float*)d_in[3];        // kernel_attention [128,1]
    float*              O   = (float*)d_out;

    gat_detect_kernel<<<1, 32>>>(E32);
    gat_unpack_kernel<<<(N_EDGES + 255) / 256, 256>>>(E32);
    gat_gemm_kernel<<<N_NODES / TM, 256>>>(X, K, KA);
    gat_rowptr_kernel<<<(N_EDGES + 255) / 256, 256>>>();
    gat_attn_kernel<<<(N_NODES * 32 + 255) / 256, 256>>>(O);
}